// round 1
// baseline (speedup 1.0000x reference)
#include <cuda_runtime.h>
#include <cuda_bf16.h>

#define D_MODEL 1024
#define HEADS   16
#define DEPTH   64
#define BATCH   4
#define SEQ     2048
#define MROWS   (BATCH * SEQ)   /* 8192 */
#define BH      (BATCH * HEADS) /* 64   */

// ---- static scratch (allocation-free per harness rules) ----
__device__ float Qg[(size_t)BH * SEQ * DEPTH];   // [bh][s][d]
__device__ float Kg[(size_t)BH * SEQ * DEPTH];
__device__ float Vg[(size_t)BH * SEQ * DEPTH];
__device__ float Og[(size_t)BH * SEQ * DEPTH];
__device__ float Sg[(size_t)BH * SEQ * SEQ];     // 1 GiB score slab

// ============================================================
// Kernel 1: projection GEMM  out_heads = heads(x @ W + b)
//   M=8192, N=1024, K=1024.  128x128x8 tile, 8x8 microtile.
//   sel: 0->Qg 1->Kg 2->Vg
// ============================================================
__global__ __launch_bounds__(256) void proj_heads_kernel(
    const float* __restrict__ x, const float* __restrict__ w,
    const float* __restrict__ bias, int sel)
{
    float* out = (sel == 0) ? Qg : (sel == 1) ? Kg : Vg;

    __shared__ float As[8][128];   // transposed: As[k][m]
    __shared__ float Bs[8][128];   // Bs[k][n]

    const int tid = threadIdx.x;
    const int m0 = blockIdx.y * 128;
    const int n0 = blockIdx.x * 128;

    const int arow = tid >> 1;          // 0..127
    const int acol = (tid & 1) * 4;     // 0 or 4
    const int brow = tid >> 5;          // 0..7
    const int bcol = (tid & 31) * 4;    // 0..124

    const int ty = tid >> 4;            // 0..15
    const int tx = tid & 15;            // 0..15

    float acc[8][8];
#pragma unroll
    for (int i = 0; i < 8; i++)
#pragma unroll
        for (int j = 0; j < 8; j++) acc[i][j] = 0.f;

    for (int k0 = 0; k0 < D_MODEL; k0 += 8) {
        float4 av = *(const float4*)&x[(size_t)(m0 + arow) * D_MODEL + k0 + acol];
        As[acol + 0][arow] = av.x;
        As[acol + 1][arow] = av.y;
        As[acol + 2][arow] = av.z;
        As[acol + 3][arow] = av.w;
        float4 bv = *(const float4*)&w[(size_t)(k0 + brow) * D_MODEL + n0 + bcol];
        *(float4*)&Bs[brow][bcol] = bv;
        __syncthreads();

#pragma unroll
        for (int k = 0; k < 8; k++) {
            float a[8], bb[8];
#pragma unroll
            for (int i = 0; i < 8; i++) a[i] = As[k][ty * 8 + i];
#pragma unroll
            for (int j = 0; j < 8; j++) bb[j] = Bs[k][tx * 8 + j];
#pragma unroll
            for (int i = 0; i < 8; i++)
#pragma unroll
                for (int j = 0; j < 8; j++) acc[i][j] += a[i] * bb[j];
        }
        __syncthreads();
    }

    // write out with head transpose: [b, s, h*64+d] -> [(b*H+h), s, d]
#pragma unroll
    for (int i = 0; i < 8; i++) {
        int m = m0 + ty * 8 + i;
        int bb = m >> 11;        // / 2048
        int ss = m & 2047;
#pragma unroll
        for (int j = 0; j < 8; j++) {
            int n = n0 + tx * 8 + j;
            int h = n >> 6;
            int d = n & 63;
            out[(((size_t)(bb * HEADS + h)) * SEQ + ss) * DEPTH + d] =
                acc[i][j] + bias[n];
        }
    }
}

// ============================================================
// Kernel 2: scores  S[bh][i][j] = 0.125 * sum_d Q[i][d]*K[j][d]
//   NT GEMM, M=N=2048, K=64, batched over 64 bh (blockIdx.z)
// ============================================================
__global__ __launch_bounds__(256) void scores_kernel()
{
    const int bh = blockIdx.z;
    const float* Q = Qg + (size_t)bh * SEQ * DEPTH;
    const float* K = Kg + (size_t)bh * SEQ * DEPTH;
    float* Srow = Sg + (size_t)bh * SEQ * SEQ;

    __shared__ float As[8][128];   // As[d][i]
    __shared__ float Bs[8][128];   // Bs[d][j]

    const int tid = threadIdx.x;
    const int m0 = blockIdx.y * 128;
    const int n0 = blockIdx.x * 128;

    const int arow = tid >> 1;
    const int acol = (tid & 1) * 4;
    const int ty = tid >> 4;
    const int tx = tid & 15;

    float acc[8][8];
#pragma unroll
    for (int i = 0; i < 8; i++)
#pragma unroll
        for (int j = 0; j < 8; j++) acc[i][j] = 0.f;

    for (int k0 = 0; k0 < DEPTH; k0 += 8) {
        float4 av = *(const float4*)&Q[(size_t)(m0 + arow) * DEPTH + k0 + acol];
        As[acol + 0][arow] = av.x;
        As[acol + 1][arow] = av.y;
        As[acol + 2][arow] = av.z;
        As[acol + 3][arow] = av.w;
        float4 kv = *(const float4*)&K[(size_t)(n0 + arow) * DEPTH + k0 + acol];
        Bs[acol + 0][arow] = kv.x;
        Bs[acol + 1][arow] = kv.y;
        Bs[acol + 2][arow] = kv.z;
        Bs[acol + 3][arow] = kv.w;
        __syncthreads();

#pragma unroll
        for (int k = 0; k < 8; k++) {
            float a[8], bb[8];
#pragma unroll
            for (int i = 0; i < 8; i++) a[i] = As[k][ty * 8 + i];
#pragma unroll
            for (int j = 0; j < 8; j++) bb[j] = Bs[k][tx * 8 + j];
#pragma unroll
            for (int i = 0; i < 8; i++)
#pragma unroll
                for (int j = 0; j < 8; j++) acc[i][j] += a[i] * bb[j];
        }
        __syncthreads();
    }

#pragma unroll
    for (int i = 0; i < 8; i++) {
        int mi = m0 + ty * 8 + i;
#pragma unroll
        for (int j = 0; j < 8; j++) {
            Srow[(size_t)mi * SEQ + n0 + tx * 8 + j] = 0.125f * acc[i][j];
        }
    }
}

// ============================================================
// Kernel 3: row softmax over Sg, one CTA (256 thr) per row of 2048
// ============================================================
__global__ __launch_bounds__(256) void softmax_kernel()
{
    const size_t row = blockIdx.x;
    float* p = Sg + row * (size_t)SEQ;
    const int tid = threadIdx.x;

    float v[8];
    float mx = -1e30f;
#pragma unroll
    for (int i = 0; i < 8; i++) {
        v[i] = p[tid + i * 256];
        mx = fmaxf(mx, v[i]);
    }

    __shared__ float red[256];
    red[tid] = mx;
    __syncthreads();
    for (int s = 128; s > 0; s >>= 1) {
        if (tid < s) red[tid] = fmaxf(red[tid], red[tid + s]);
        __syncthreads();
    }
    mx = red[0];
    __syncthreads();

    float sum = 0.f;
#pragma unroll
    for (int i = 0; i < 8; i++) {
        v[i] = __expf(v[i] - mx);
        sum += v[i];
    }
    red[tid] = sum;
    __syncthreads();
    for (int s = 128; s > 0; s >>= 1) {
        if (tid < s) red[tid] += red[tid + s];
        __syncthreads();
    }
    float inv = 1.f / red[0];
#pragma unroll
    for (int i = 0; i < 8; i++) p[tid + i * 256] = v[i] * inv;
}

// ============================================================
// Kernel 4: O = P @ V   M=2048, N=64, K=2048 per bh
//   128x64x16 tile, 8x4 microtile, 256 threads
// ============================================================
__global__ __launch_bounds__(256) void pv_kernel()
{
    const int bh = blockIdx.y;
    const float* P = Sg + (size_t)bh * SEQ * SEQ;
    const float* V = Vg + (size_t)bh * SEQ * DEPTH;
    float* O = Og + (size_t)bh * SEQ * DEPTH;

    __shared__ float As[16][128];   // As[k][m]
    __shared__ float Bs[16][64];    // Bs[k][n]

    const int tid = threadIdx.x;
    const int m0 = blockIdx.x * 128;
    const int ty = tid >> 4;        // 0..15
    const int tx = tid & 15;        // 0..15

    float acc[8][4];
#pragma unroll
    for (int i = 0; i < 8; i++)
#pragma unroll
        for (int j = 0; j < 4; j++) acc[i][j] = 0.f;

    const int brow = tid >> 4;          // 0..15
    const int bcol = (tid & 15) * 4;    // 0..60

    for (int k0 = 0; k0 < SEQ; k0 += 16) {
        // A tile 128x16 (2048 floats = 512 float4, 2 per thread)
#pragma unroll
        for (int t = 0; t < 2; t++) {
            int id = tid + t * 256;
            int r = id >> 2;
            int c = (id & 3) * 4;
            float4 av = *(const float4*)&P[(size_t)(m0 + r) * SEQ + k0 + c];
            As[c + 0][r] = av.x;
            As[c + 1][r] = av.y;
            As[c + 2][r] = av.z;
            As[c + 3][r] = av.w;
        }
        // B tile 16x64 (1024 floats = 256 float4, 1 per thread)
        float4 bv = *(const float4*)&V[(size_t)(k0 + brow) * DEPTH + bcol];
        *(float4*)&Bs[brow][bcol] = bv;
        __syncthreads();

#pragma unroll
        for (int k = 0; k < 16; k++) {
            float a[8], bb[4];
#pragma unroll
            for (int i = 0; i < 8; i++) a[i] = As[k][ty * 8 + i];
#pragma unroll
            for (int j = 0; j < 4; j++) bb[j] = Bs[k][tx * 4 + j];
#pragma unroll
            for (int i = 0; i < 8; i++)
#pragma unroll
                for (int j = 0; j < 4; j++) acc[i][j] += a[i] * bb[j];
        }
        __syncthreads();
    }

#pragma unroll
    for (int i = 0; i < 8; i++) {
        int mi = m0 + ty * 8 + i;
#pragma unroll
        for (int j = 0; j < 4; j++) {
            O[(size_t)mi * DEPTH + tx * 4 + j] = acc[i][j];
        }
    }
}

// ============================================================
// Kernel 5: out = untranspose(O) @ Wo + bo
//   A gathered from [bh][s][d] layout. M=8192, N=1024, K=1024.
// ============================================================
__global__ __launch_bounds__(256) void outproj_kernel(
    const float* __restrict__ wo, const float* __restrict__ bo,
    float* __restrict__ out)
{
    __shared__ float As[8][128];
    __shared__ float Bs[8][128];

    const int tid = threadIdx.x;
    const int m0 = blockIdx.y * 128;
    const int n0 = blockIdx.x * 128;

    const int arow = tid >> 1;
    const int acol = (tid & 1) * 4;
    const int brow = tid >> 5;
    const int bcol = (tid & 31) * 4;
    const int ty = tid >> 4;
    const int tx = tid & 15;

    const int am = m0 + arow;
    const int ab = am >> 11;
    const int as = am & 2047;

    float acc[8][8];
#pragma unroll
    for (int i = 0; i < 8; i++)
#pragma unroll
        for (int j = 0; j < 8; j++) acc[i][j] = 0.f;

    for (int k0 = 0; k0 < D_MODEL; k0 += 8) {
        int kk = k0 + acol;
        int h = kk >> 6;
        int d = kk & 63;
        float4 av = *(const float4*)&Og[(((size_t)(ab * HEADS + h)) * SEQ + as) * DEPTH + d];
        As[acol + 0][arow] = av.x;
        As[acol + 1][arow] = av.y;
        As[acol + 2][arow] = av.z;
        As[acol + 3][arow] = av.w;
        float4 bv = *(const float4*)&wo[(size_t)(k0 + brow) * D_MODEL + n0 + bcol];
        *(float4*)&Bs[brow][bcol] = bv;
        __syncthreads();

#pragma unroll
        for (int k = 0; k < 8; k++) {
            float a[8], bb[8];
#pragma unroll
            for (int i = 0; i < 8; i++) a[i] = As[k][ty * 8 + i];
#pragma unroll
            for (int j = 0; j < 8; j++) bb[j] = Bs[k][tx * 8 + j];
#pragma unroll
            for (int i = 0; i < 8; i++)
#pragma unroll
                for (int j = 0; j < 8; j++) acc[i][j] += a[i] * bb[j];
        }
        __syncthreads();
    }

#pragma unroll
    for (int i = 0; i < 8; i++) {
        int m = m0 + ty * 8 + i;
#pragma unroll
        for (int j = 0; j < 8; j++) {
            int n = n0 + tx * 8 + j;
            out[(size_t)m * D_MODEL + n] = acc[i][j] + bo[n];
        }
    }
}

// ============================================================
extern "C" void kernel_launch(void* const* d_in, const int* in_sizes, int n_in,
                              void* d_out, int out_size)
{
    const float* x  = (const float*)d_in[0];
    const float* wq = (const float*)d_in[1];
    const float* bq = (const float*)d_in[2];
    const float* wk = (const float*)d_in[3];
    const float* bk = (const float*)d_in[4];
    const float* wv = (const float*)d_in[5];
    const float* bv = (const float*)d_in[6];
    const float* wo = (const float*)d_in[7];
    const float* bo = (const float*)d_in[8];
    float* out = (float*)d_out;

    dim3 blk(256);
    dim3 gproj(D_MODEL / 128, MROWS / 128);            // (8, 64)

    proj_heads_kernel<<<gproj, blk>>>(x, wq, bq, 0);
    proj_heads_kernel<<<gproj, blk>>>(x, wk, bk, 1);
    proj_heads_kernel<<<gproj, blk>>>(x, wv, bv, 2);

    scores_kernel<<<dim3(SEQ / 128, SEQ / 128, BH), blk>>>();   // (16,16,64)

    softmax_kernel<<<dim3(BH * SEQ), blk>>>();                  // 131072 rows

    pv_kernel<<<dim3(SEQ / 128, BH), blk>>>();                  // (16, 64)

    outproj_kernel<<<gproj, blk>>>(wo, bo, out);
}

// round 2
// speedup vs baseline: 3.0602x; 3.0602x over previous
#include <cuda_runtime.h>
#include <cuda_bf16.h>

#define D_MODEL 1024
#define HEADS   16
#define DEPTH   64
#define BATCH   4
#define SEQ     2048
#define MROWS   (BATCH * SEQ)   /* 8192 */
#define BH      (BATCH * HEADS) /* 64   */

// ---- static scratch (allocation-free per harness rules) ----
__device__ float Qg[(size_t)BH * SEQ * DEPTH];   // [bh][s][d], tf32-rounded
__device__ float Kg[(size_t)BH * SEQ * DEPTH];
__device__ float Vg[(size_t)BH * SEQ * DEPTH];
__device__ float Og[(size_t)BH * SEQ * DEPTH];   // tf32-rounded
__device__ float Sg[(size_t)BH * SEQ * SEQ];     // 1 GiB score/prob slab
__device__ float Xr[(size_t)MROWS * D_MODEL];    // x rounded to tf32
__device__ float Wr[(size_t)4 * D_MODEL * D_MODEL]; // wq,wk,wv,wo rounded

// ---------------- helpers ----------------
__device__ __forceinline__ unsigned su(const void* p) {
    return (unsigned)__cvta_generic_to_shared(p);
}
__device__ __forceinline__ void cp16(unsigned d, const void* s) {
    asm volatile("cp.async.cg.shared.global [%0], [%1], 16;" :: "r"(d), "l"(s));
}
__device__ __forceinline__ void cpcommit() { asm volatile("cp.async.commit_group;"); }
__device__ __forceinline__ void cpwait0() { asm volatile("cp.async.wait_group 0;"); }
__device__ __forceinline__ void cpwait1() { asm volatile("cp.async.wait_group 1;"); }

__device__ __forceinline__ float tf32r(float x) {
    unsigned u;
    asm("cvt.rna.tf32.f32 %0, %1;" : "=r"(u) : "f"(x));
    return __uint_as_float(u);
}
__device__ __forceinline__ void mma8(float* c, const unsigned* a, const unsigned* b) {
    asm volatile(
        "mma.sync.aligned.m16n8k8.row.col.f32.tf32.tf32.f32 "
        "{%0,%1,%2,%3},{%4,%5,%6,%7},{%8,%9},{%0,%1,%2,%3};"
        : "+f"(c[0]), "+f"(c[1]), "+f"(c[2]), "+f"(c[3])
        : "r"(a[0]), "r"(a[1]), "r"(a[2]), "r"(a[3]), "r"(b[0]), "r"(b[1]));
}

// ---------------- kernel 0: round fp32 -> tf32 (vectorized) ----------------
__global__ __launch_bounds__(256) void round_tf32_kernel(
    const float* __restrict__ in, float* __restrict__ out, int n4)
{
    int i = blockIdx.x * 256 + threadIdx.x;
    if (i < n4) {
        float4 v = ((const float4*)in)[i];
        v.x = tf32r(v.x); v.y = tf32r(v.y); v.z = tf32r(v.z); v.w = tf32r(v.w);
        ((float4*)out)[i] = v;
    }
}

// ============================================================
// Kernel 1: proj  out_heads = heads(Xr @ Wr + b), tf32 mma
//   M=8192, N=1024, K=1024.  CTA 128x128x32, 8 warps (32x64 each).
// ============================================================
__global__ __launch_bounds__(256) void proj_tc_kernel(
    const float* __restrict__ A, const float* __restrict__ W,
    const float* __restrict__ bias, float* __restrict__ out)
{
    extern __shared__ float sm[];
    float* Asm[2] = { sm, sm + 4608 };            // 128 rows x stride 36
    float* Bsm[2] = { sm + 9216, sm + 9216 + 4352 }; // 32 rows x stride 136

    const int tid = threadIdx.x;
    const int m0 = blockIdx.y * 128, n0 = blockIdx.x * 128;
    const int warp = tid >> 5, lane = tid & 31;
    const int g = lane >> 2, t = lane & 3;
    const int wm = (warp & 3) * 32, wn = (warp >> 2) * 64;

    float acc[2][8][4] = {};

#define PROJ_LOAD(buf, k0)                                                        \
    do {                                                                          \
        _Pragma("unroll")                                                         \
        for (int i = 0; i < 4; i++) {                                             \
            int id = tid + i * 256; int r = id >> 3, cc = id & 7;                 \
            cp16(su(&Asm[buf][r * 36 + cc * 4]),                                  \
                 A + (size_t)(m0 + r) * 1024 + (k0) + cc * 4);                    \
        }                                                                         \
        _Pragma("unroll")                                                         \
        for (int i = 0; i < 4; i++) {                                             \
            int id = tid + i * 256; int r = id >> 5, cc = id & 31;                \
            cp16(su(&Bsm[buf][r * 136 + cc * 4]),                                 \
                 W + (size_t)((k0) + r) * 1024 + n0 + cc * 4);                    \
        }                                                                         \
        cpcommit();                                                               \
    } while (0)

    PROJ_LOAD(0, 0);
    for (int it = 0; it < 32; it++) {
        if (it + 1 < 32) { PROJ_LOAD((it + 1) & 1, (it + 1) * 32); cpwait1(); }
        else cpwait0();
        __syncthreads();
        const float* a_s = Asm[it & 1];
        const float* b_s = Bsm[it & 1];
#pragma unroll
        for (int ks = 0; ks < 32; ks += 8) {
            unsigned a[2][4], b[8][2];
#pragma unroll
            for (int ma = 0; ma < 2; ma++) {
                int rb = wm + ma * 16;
                a[ma][0] = __float_as_uint(a_s[(rb + g) * 36 + ks + t]);
                a[ma][1] = __float_as_uint(a_s[(rb + g + 8) * 36 + ks + t]);
                a[ma][2] = __float_as_uint(a_s[(rb + g) * 36 + ks + t + 4]);
                a[ma][3] = __float_as_uint(a_s[(rb + g + 8) * 36 + ks + t + 4]);
            }
#pragma unroll
            for (int nb = 0; nb < 8; nb++) {
                b[nb][0] = __float_as_uint(b_s[(ks + t) * 136 + wn + nb * 8 + g]);
                b[nb][1] = __float_as_uint(b_s[(ks + t + 4) * 136 + wn + nb * 8 + g]);
            }
#pragma unroll
            for (int nb = 0; nb < 8; nb++)
#pragma unroll
                for (int ma = 0; ma < 2; ma++)
                    mma8(acc[ma][nb], a[ma], b[nb]);
        }
        __syncthreads();
    }

    // epilogue: +bias, round to tf32, head transpose [b,s,h*64+d] -> [bh][s][d]
#pragma unroll
    for (int ma = 0; ma < 2; ma++)
#pragma unroll
        for (int nb = 0; nb < 8; nb++) {
            int c0 = n0 + wn + nb * 8 + t * 2;
            float b0 = __ldg(&bias[c0]), b1 = __ldg(&bias[c0 + 1]);
            int h = c0 >> 6, d = c0 & 63;
#pragma unroll
            for (int rr = 0; rr < 2; rr++) {
                int r = m0 + wm + ma * 16 + g + rr * 8;
                int bb = r >> 11, ss = r & 2047;
                float2 v;
                v.x = tf32r(acc[ma][nb][rr * 2 + 0] + b0);
                v.y = tf32r(acc[ma][nb][rr * 2 + 1] + b1);
                *(float2*)&out[(((size_t)(bb * 16 + h)) * 2048 + ss) * 64 + d] = v;
            }
        }
}

// ============================================================
// Kernel 2: scores  S = 0.125 * Q K^T  (NT, K=64, one shot)
// ============================================================
__global__ __launch_bounds__(256) void scores_tc_kernel()
{
    extern __shared__ float sm[];
    float* Qs = sm;          // 128 x stride 72
    float* Ks = sm + 9216;   // 128 x stride 72

    const int bh = blockIdx.z;
    const float* Q = Qg + (size_t)bh * SEQ * DEPTH;
    const float* Kp = Kg + (size_t)bh * SEQ * DEPTH;
    float* S = Sg + (size_t)bh * SEQ * SEQ;

    const int tid = threadIdx.x;
    const int m0 = blockIdx.y * 128, n0 = blockIdx.x * 128;
    const int warp = tid >> 5, lane = tid & 31;
    const int g = lane >> 2, t = lane & 3;
    const int wm = (warp & 3) * 32, wn = (warp >> 2) * 64;

#pragma unroll
    for (int i = 0; i < 8; i++) {
        int id = tid + i * 256; int r = id >> 4, cc = id & 15;
        cp16(su(&Qs[r * 72 + cc * 4]), Q + (size_t)(m0 + r) * 64 + cc * 4);
    }
#pragma unroll
    for (int i = 0; i < 8; i++) {
        int id = tid + i * 256; int r = id >> 4, cc = id & 15;
        cp16(su(&Ks[r * 72 + cc * 4]), Kp + (size_t)(n0 + r) * 64 + cc * 4);
    }
    cpcommit(); cpwait0();
    __syncthreads();

    float acc[2][8][4] = {};
#pragma unroll
    for (int ks = 0; ks < 64; ks += 8) {
        unsigned a[2][4], b[8][2];
#pragma unroll
        for (int ma = 0; ma < 2; ma++) {
            int rb = wm + ma * 16;
            a[ma][0] = __float_as_uint(Qs[(rb + g) * 72 + ks + t]);
            a[ma][1] = __float_as_uint(Qs[(rb + g + 8) * 72 + ks + t]);
            a[ma][2] = __float_as_uint(Qs[(rb + g) * 72 + ks + t + 4]);
            a[ma][3] = __float_as_uint(Qs[(rb + g + 8) * 72 + ks + t + 4]);
        }
#pragma unroll
        for (int nb = 0; nb < 8; nb++) {
            int nr = wn + nb * 8 + g;
            b[nb][0] = __float_as_uint(Ks[nr * 72 + ks + t]);
            b[nb][1] = __float_as_uint(Ks[nr * 72 + ks + t + 4]);
        }
#pragma unroll
        for (int nb = 0; nb < 8; nb++)
#pragma unroll
            for (int ma = 0; ma < 2; ma++)
                mma8(acc[ma][nb], a[ma], b[nb]);
    }

#pragma unroll
    for (int ma = 0; ma < 2; ma++)
#pragma unroll
        for (int nb = 0; nb < 8; nb++) {
            int c0 = n0 + wn + nb * 8 + t * 2;
#pragma unroll
            for (int rr = 0; rr < 2; rr++) {
                int r = m0 + wm + ma * 16 + g + rr * 8;
                float2 v;
                v.x = 0.125f * acc[ma][nb][rr * 2 + 0];
                v.y = 0.125f * acc[ma][nb][rr * 2 + 1];
                *(float2*)&S[(size_t)r * SEQ + c0] = v;
            }
        }
}

// ============================================================
// Kernel 3: row softmax (rounds P to tf32 at store)
// ============================================================
__global__ __launch_bounds__(256) void softmax_kernel()
{
    const size_t row = blockIdx.x;
    float* p = Sg + row * (size_t)SEQ;
    const int tid = threadIdx.x;

    float v[8];
    float mx = -1e30f;
#pragma unroll
    for (int i = 0; i < 8; i++) { v[i] = p[tid + i * 256]; mx = fmaxf(mx, v[i]); }

    __shared__ float red[256];
    red[tid] = mx; __syncthreads();
    for (int s = 128; s > 0; s >>= 1) {
        if (tid < s) red[tid] = fmaxf(red[tid], red[tid + s]);
        __syncthreads();
    }
    mx = red[0]; __syncthreads();

    float sum = 0.f;
#pragma unroll
    for (int i = 0; i < 8; i++) { v[i] = __expf(v[i] - mx); sum += v[i]; }
    red[tid] = sum; __syncthreads();
    for (int s = 128; s > 0; s >>= 1) {
        if (tid < s) red[tid] += red[tid + s];
        __syncthreads();
    }
    float inv = 1.f / red[0];
#pragma unroll
    for (int i = 0; i < 8; i++) p[tid + i * 256] = tf32r(v[i] * inv);
}

// ============================================================
// Kernel 4: O = P @ V  (M=2048,N=64,K=2048 per bh), tf32 mma
//   CTA 128x64x32, 8 warps (32x32 each)
// ============================================================
__global__ __launch_bounds__(256) void pv_tc_kernel()
{
    extern __shared__ float sm[];
    float* Asm[2] = { sm, sm + 4608 };            // 128 x stride 36
    float* Bsm[2] = { sm + 9216, sm + 9216 + 2304 }; // 32 x stride 72

    const int bh = blockIdx.y;
    const float* P = Sg + (size_t)bh * SEQ * SEQ;
    const float* V = Vg + (size_t)bh * SEQ * DEPTH;
    float* O = Og + (size_t)bh * SEQ * DEPTH;

    const int tid = threadIdx.x;
    const int m0 = blockIdx.x * 128;
    const int warp = tid >> 5, lane = tid & 31;
    const int g = lane >> 2, t = lane & 3;
    const int wm = (warp & 3) * 32, wn = (warp >> 2) * 32;

    float acc[2][4][4] = {};

#define PV_LOAD(buf, k0)                                                          \
    do {                                                                          \
        _Pragma("unroll")                                                         \
        for (int i = 0; i < 4; i++) {                                             \
            int id = tid + i * 256; int r = id >> 3, cc = id & 7;                 \
            cp16(su(&Asm[buf][r * 36 + cc * 4]),                                  \
                 P + (size_t)(m0 + r) * SEQ + (k0) + cc * 4);                     \
        }                                                                         \
        _Pragma("unroll")                                                         \
        for (int i = 0; i < 2; i++) {                                             \
            int id = tid + i * 256; int r = id >> 4, cc = id & 15;                \
            cp16(su(&Bsm[buf][r * 72 + cc * 4]),                                  \
                 V + (size_t)((k0) + r) * 64 + cc * 4);                           \
        }                                                                         \
        cpcommit();                                                               \
    } while (0)

    PV_LOAD(0, 0);
    for (int it = 0; it < 64; it++) {
        if (it + 1 < 64) { PV_LOAD((it + 1) & 1, (it + 1) * 32); cpwait1(); }
        else cpwait0();
        __syncthreads();
        const float* a_s = Asm[it & 1];
        const float* b_s = Bsm[it & 1];
#pragma unroll
        for (int ks = 0; ks < 32; ks += 8) {
            unsigned a[2][4], b[4][2];
#pragma unroll
            for (int ma = 0; ma < 2; ma++) {
                int rb = wm + ma * 16;
                a[ma][0] = __float_as_uint(a_s[(rb + g) * 36 + ks + t]);
                a[ma][1] = __float_as_uint(a_s[(rb + g + 8) * 36 + ks + t]);
                a[ma][2] = __float_as_uint(a_s[(rb + g) * 36 + ks + t + 4]);
                a[ma][3] = __float_as_uint(a_s[(rb + g + 8) * 36 + ks + t + 4]);
            }
#pragma unroll
            for (int nb = 0; nb < 4; nb++) {
                b[nb][0] = __float_as_uint(b_s[(ks + t) * 72 + wn + nb * 8 + g]);
                b[nb][1] = __float_as_uint(b_s[(ks + t + 4) * 72 + wn + nb * 8 + g]);
            }
#pragma unroll
            for (int nb = 0; nb < 4; nb++)
#pragma unroll
                for (int ma = 0; ma < 2; ma++)
                    mma8(acc[ma][nb], a[ma], b[nb]);
        }
        __syncthreads();
    }

#pragma unroll
    for (int ma = 0; ma < 2; ma++)
#pragma unroll
        for (int nb = 0; nb < 4; nb++) {
            int c0 = wn + nb * 8 + t * 2;
#pragma unroll
            for (int rr = 0; rr < 2; rr++) {
                int r = m0 + wm + ma * 16 + g + rr * 8;
                float2 v;
                v.x = tf32r(acc[ma][nb][rr * 2 + 0]);
                v.y = tf32r(acc[ma][nb][rr * 2 + 1]);
                *(float2*)&O[(size_t)r * 64 + c0] = v;
            }
        }
}

// ============================================================
// Kernel 5: out = untranspose(Og) @ wo + bo, tf32 mma
// ============================================================
__global__ __launch_bounds__(256) void outproj_tc_kernel(
    const float* __restrict__ W, const float* __restrict__ bo,
    float* __restrict__ out)
{
    extern __shared__ float sm[];
    float* Asm[2] = { sm, sm + 4608 };
    float* Bsm[2] = { sm + 9216, sm + 9216 + 4352 };

    const int tid = threadIdx.x;
    const int m0 = blockIdx.y * 128, n0 = blockIdx.x * 128;
    const int warp = tid >> 5, lane = tid & 31;
    const int g = lane >> 2, t = lane & 3;
    const int wm = (warp & 3) * 32, wn = (warp >> 2) * 64;

    float acc[2][8][4] = {};

#define OP_LOAD(buf, k0)                                                          \
    do {                                                                          \
        _Pragma("unroll")                                                         \
        for (int i = 0; i < 4; i++) {                                             \
            int id = tid + i * 256; int r = id >> 3, cc = id & 7;                 \
            int m = m0 + r; int k = (k0) + cc * 4;                                \
            const float* src = Og + (((size_t)((m >> 11) * 16 + (k >> 6))) * 2048 \
                                     + (m & 2047)) * 64 + (k & 63);               \
            cp16(su(&Asm[buf][r * 36 + cc * 4]), src);                            \
        }                                                                         \
        _Pragma("unroll")                                                         \
        for (int i = 0; i < 4; i++) {                                             \
            int id = tid + i * 256; int r = id >> 5, cc = id & 31;                \
            cp16(su(&Bsm[buf][r * 136 + cc * 4]),                                 \
                 W + (size_t)((k0) + r) * 1024 + n0 + cc * 4);                    \
        }                                                                         \
        cpcommit();                                                               \
    } while (0)

    OP_LOAD(0, 0);
    for (int it = 0; it < 32; it++) {
        if (it + 1 < 32) { OP_LOAD((it + 1) & 1, (it + 1) * 32); cpwait1(); }
        else cpwait0();
        __syncthreads();
        const float* a_s = Asm[it & 1];
        const float* b_s = Bsm[it & 1];
#pragma unroll
        for (int ks = 0; ks < 32; ks += 8) {
            unsigned a[2][4], b[8][2];
#pragma unroll
            for (int ma = 0; ma < 2; ma++) {
                int rb = wm + ma * 16;
                a[ma][0] = __float_as_uint(a_s[(rb + g) * 36 + ks + t]);
                a[ma][1] = __float_as_uint(a_s[(rb + g + 8) * 36 + ks + t]);
                a[ma][2] = __float_as_uint(a_s[(rb + g) * 36 + ks + t + 4]);
                a[ma][3] = __float_as_uint(a_s[(rb + g + 8) * 36 + ks + t + 4]);
            }
#pragma unroll
            for (int nb = 0; nb < 8; nb++) {
                b[nb][0] = __float_as_uint(b_s[(ks + t) * 136 + wn + nb * 8 + g]);
                b[nb][1] = __float_as_uint(b_s[(ks + t + 4) * 136 + wn + nb * 8 + g]);
            }
#pragma unroll
            for (int nb = 0; nb < 8; nb++)
#pragma unroll
                for (int ma = 0; ma < 2; ma++)
                    mma8(acc[ma][nb], a[ma], b[nb]);
        }
        __syncthreads();
    }

#pragma unroll
    for (int ma = 0; ma < 2; ma++)
#pragma unroll
        for (int nb = 0; nb < 8; nb++) {
            int c0 = n0 + wn + nb * 8 + t * 2;
            float b0 = __ldg(&bo[c0]), b1 = __ldg(&bo[c0 + 1]);
#pragma unroll
            for (int rr = 0; rr < 2; rr++) {
                int r = m0 + wm + ma * 16 + g + rr * 8;
                float2 v;
                v.x = acc[ma][nb][rr * 2 + 0] + b0;
                v.y = acc[ma][nb][rr * 2 + 1] + b1;
                *(float2*)&out[(size_t)r * 1024 + c0] = v;
            }
        }
}

// ============================================================
extern "C" void kernel_launch(void* const* d_in, const int* in_sizes, int n_in,
                              void* d_out, int out_size)
{
    const float* x  = (const float*)d_in[0];
    const float* wq = (const float*)d_in[1];
    const float* bq = (const float*)d_in[2];
    const float* wk = (const float*)d_in[3];
    const float* bk = (const float*)d_in[4];
    const float* wv = (const float*)d_in[5];
    const float* bv = (const float*)d_in[6];
    const float* wo = (const float*)d_in[7];
    const float* bo = (const float*)d_in[8];
    float* out = (float*)d_out;

    cudaFuncSetAttribute(proj_tc_kernel,    cudaFuncAttributeMaxDynamicSharedMemorySize, 71680);
    cudaFuncSetAttribute(scores_tc_kernel,  cudaFuncAttributeMaxDynamicSharedMemorySize, 73728);
    cudaFuncSetAttribute(pv_tc_kernel,      cudaFuncAttributeMaxDynamicSharedMemorySize, 55296);
    cudaFuncSetAttribute(outproj_tc_kernel, cudaFuncAttributeMaxDynamicSharedMemorySize, 71680);

    float* Xr_p; cudaGetSymbolAddress((void**)&Xr_p, Xr);
    float* Wr_p; cudaGetSymbolAddress((void**)&Wr_p, Wr);
    float* Qp;   cudaGetSymbolAddress((void**)&Qp, Qg);
    float* Kp;   cudaGetSymbolAddress((void**)&Kp, Kg);
    float* Vp;   cudaGetSymbolAddress((void**)&Vp, Vg);

    dim3 blk(256);
    const size_t WSZ = (size_t)D_MODEL * D_MODEL;

    // round inputs/weights to tf32 once
    {
        int n4 = (MROWS * D_MODEL) / 4;
        round_tf32_kernel<<<(n4 + 255) / 256, blk>>>(x, Xr_p, n4);
        int w4 = (int)(WSZ / 4);
        round_tf32_kernel<<<(w4 + 255) / 256, blk>>>(wq, Wr_p + 0 * WSZ, w4);
        round_tf32_kernel<<<(w4 + 255) / 256, blk>>>(wk, Wr_p + 1 * WSZ, w4);
        round_tf32_kernel<<<(w4 + 255) / 256, blk>>>(wv, Wr_p + 2 * WSZ, w4);
        round_tf32_kernel<<<(w4 + 255) / 256, blk>>>(wo, Wr_p + 3 * WSZ, w4);
    }

    dim3 gproj(D_MODEL / 128, MROWS / 128);  // (8, 64)
    proj_tc_kernel<<<gproj, blk, 71680>>>(Xr_p, Wr_p + 0 * WSZ, bq, Qp);
    proj_tc_kernel<<<gproj, blk, 71680>>>(Xr_p, Wr_p + 1 * WSZ, bk, Kp);
    proj_tc_kernel<<<gproj, blk, 71680>>>(Xr_p, Wr_p + 2 * WSZ, bv, Vp);

    scores_tc_kernel<<<dim3(SEQ / 128, SEQ / 128, BH), blk, 73728>>>();

    softmax_kernel<<<dim3(BH * SEQ), blk>>>();

    pv_tc_kernel<<<dim3(SEQ / 128, BH), blk, 55296>>>();

    outproj_tc_kernel<<<gproj, blk, 71680>>>(Wr_p + 3 * WSZ, bo, out);
}

// round 3
// speedup vs baseline: 3.9738x; 1.2986x over previous
#include <cuda_runtime.h>
#include <cuda_bf16.h>

#define D_MODEL 1024
#define HEADS   16
#define DEPTH   64
#define BATCH   4
#define SEQ     2048
#define MROWS   (BATCH * SEQ)   /* 8192 */
#define BH      (BATCH * HEADS) /* 64   */

// ---- static scratch (allocation-free per harness rules) ----
__device__ float Qg[(size_t)BH * SEQ * DEPTH];   // [bh][s][d], tf32-rounded
__device__ float Kg[(size_t)BH * SEQ * DEPTH];
__device__ float Vg[(size_t)BH * SEQ * DEPTH];
__device__ float Og[(size_t)BH * SEQ * DEPTH];   // attention out, tf32-rounded
__device__ float Xr[(size_t)MROWS * D_MODEL];    // x rounded to tf32
__device__ float Wr[(size_t)4 * D_MODEL * D_MODEL]; // wq,wk,wv,wo rounded

// ---------------- helpers ----------------
__device__ __forceinline__ unsigned su(const void* p) {
    return (unsigned)__cvta_generic_to_shared(p);
}
__device__ __forceinline__ void cp16(unsigned d, const void* s) {
    asm volatile("cp.async.cg.shared.global [%0], [%1], 16;" :: "r"(d), "l"(s));
}
__device__ __forceinline__ void cpcommit() { asm volatile("cp.async.commit_group;"); }
__device__ __forceinline__ void cpwait0() { asm volatile("cp.async.wait_group 0;"); }
__device__ __forceinline__ void cpwait1() { asm volatile("cp.async.wait_group 1;"); }

__device__ __forceinline__ float tf32r(float x) {
    unsigned u;
    asm("cvt.rna.tf32.f32 %0, %1;" : "=r"(u) : "f"(x));
    return __uint_as_float(u);
}
__device__ __forceinline__ void mma8(float* c, const unsigned* a, const unsigned* b) {
    asm volatile(
        "mma.sync.aligned.m16n8k8.row.col.f32.tf32.tf32.f32 "
        "{%0,%1,%2,%3},{%4,%5,%6,%7},{%8,%9},{%0,%1,%2,%3};"
        : "+f"(c[0]), "+f"(c[1]), "+f"(c[2]), "+f"(c[3])
        : "r"(a[0]), "r"(a[1]), "r"(a[2]), "r"(a[3]), "r"(b[0]), "r"(b[1]));
}

// ---------------- kernel 0: round fp32 -> tf32 (vectorized) ----------------
__global__ __launch_bounds__(256) void round_tf32_kernel(
    const float* __restrict__ in, float* __restrict__ out, int n4)
{
    int i = blockIdx.x * 256 + threadIdx.x;
    if (i < n4) {
        float4 v = ((const float4*)in)[i];
        v.x = tf32r(v.x); v.y = tf32r(v.y); v.z = tf32r(v.z); v.w = tf32r(v.w);
        ((float4*)out)[i] = v;
    }
}

// ============================================================
// Kernel 1: proj  out_heads = heads(Xr @ Wr + b), tf32 mma
// ============================================================
__global__ __launch_bounds__(256) void proj_tc_kernel(
    const float* __restrict__ A, const float* __restrict__ W,
    const float* __restrict__ bias, float* __restrict__ out)
{
    extern __shared__ float sm[];
    float* Asm[2] = { sm, sm + 4608 };            // 128 rows x stride 36
    float* Bsm[2] = { sm + 9216, sm + 9216 + 4352 }; // 32 rows x stride 136

    const int tid = threadIdx.x;
    const int m0 = blockIdx.y * 128, n0 = blockIdx.x * 128;
    const int warp = tid >> 5, lane = tid & 31;
    const int g = lane >> 2, t = lane & 3;
    const int wm = (warp & 3) * 32, wn = (warp >> 2) * 64;

    float acc[2][8][4] = {};

#define PROJ_LOAD(buf, k0)                                                        \
    do {                                                                          \
        _Pragma("unroll")                                                         \
        for (int i = 0; i < 4; i++) {                                             \
            int id = tid + i * 256; int r = id >> 3, cc = id & 7;                 \
            cp16(su(&Asm[buf][r * 36 + cc * 4]),                                  \
                 A + (size_t)(m0 + r) * 1024 + (k0) + cc * 4);                    \
        }                                                                         \
        _Pragma("unroll")                                                         \
        for (int i = 0; i < 4; i++) {                                             \
            int id = tid + i * 256; int r = id >> 5, cc = id & 31;                \
            cp16(su(&Bsm[buf][r * 136 + cc * 4]),                                 \
                 W + (size_t)((k0) + r) * 1024 + n0 + cc * 4);                    \
        }                                                                         \
        cpcommit();                                                               \
    } while (0)

    PROJ_LOAD(0, 0);
    for (int it = 0; it < 32; it++) {
        if (it + 1 < 32) { PROJ_LOAD((it + 1) & 1, (it + 1) * 32); cpwait1(); }
        else cpwait0();
        __syncthreads();
        const float* a_s = Asm[it & 1];
        const float* b_s = Bsm[it & 1];
#pragma unroll
        for (int ks = 0; ks < 32; ks += 8) {
            unsigned a[2][4], b[8][2];
#pragma unroll
            for (int ma = 0; ma < 2; ma++) {
                int rb = wm + ma * 16;
                a[ma][0] = __float_as_uint(a_s[(rb + g) * 36 + ks + t]);
                a[ma][1] = __float_as_uint(a_s[(rb + g + 8) * 36 + ks + t]);
                a[ma][2] = __float_as_uint(a_s[(rb + g) * 36 + ks + t + 4]);
                a[ma][3] = __float_as_uint(a_s[(rb + g + 8) * 36 + ks + t + 4]);
            }
#pragma unroll
            for (int nb = 0; nb < 8; nb++) {
                b[nb][0] = __float_as_uint(b_s[(ks + t) * 136 + wn + nb * 8 + g]);
                b[nb][1] = __float_as_uint(b_s[(ks + t + 4) * 136 + wn + nb * 8 + g]);
            }
#pragma unroll
            for (int nb = 0; nb < 8; nb++)
#pragma unroll
                for (int ma = 0; ma < 2; ma++)
                    mma8(acc[ma][nb], a[ma], b[nb]);
        }
        __syncthreads();
    }

    // epilogue: +bias, round to tf32, head transpose [b,s,h*64+d] -> [bh][s][d]
#pragma unroll
    for (int ma = 0; ma < 2; ma++)
#pragma unroll
        for (int nb = 0; nb < 8; nb++) {
            int c0 = n0 + wn + nb * 8 + t * 2;
            float b0 = __ldg(&bias[c0]), b1 = __ldg(&bias[c0 + 1]);
            int h = c0 >> 6, d = c0 & 63;
#pragma unroll
            for (int rr = 0; rr < 2; rr++) {
                int r = m0 + wm + ma * 16 + g + rr * 8;
                int bb = r >> 11, ss = r & 2047;
                float2 v;
                v.x = tf32r(acc[ma][nb][rr * 2 + 0] + b0);
                v.y = tf32r(acc[ma][nb][rr * 2 + 1] + b1);
                *(float2*)&out[(((size_t)(bb * 16 + h)) * 2048 + ss) * 64 + d] = v;
            }
        }
}

// ============================================================
// Kernel 2: FLASH ATTENTION  (scores + softmax + PV fused)
//   CTA = 128 Q rows x one bh.  8 warps x 16 rows each.
//   Q in register fragments (pre-scaled by 0.125), K/V tiles
//   double-buffered in smem via cp.async. O accum in registers.
// ============================================================
#define QS_STRIDE 68   /* row-indexed-by-g: stride % 32 == 4 -> conflict-free */
#define KS_STRIDE 68
#define VS_STRIDE 72   /* row-indexed-by-t: stride % 32 == 8 -> conflict-free */

__global__ __launch_bounds__(256, 1) void flash_attn_kernel()
{
    extern __shared__ float sm[];
    float* Qs = sm;                                  // 128 x 68 = 8704
    float* Ks[2] = { sm + 8704, sm + 8704 + 8704 };  // each 128 x 68
    float* Vs[2] = { sm + 26112, sm + 26112 + 9216 }; // each 128 x 72

    const int bh = blockIdx.y;
    const int m0 = blockIdx.x * 128;
    const float* Qp = Qg + (size_t)bh * SEQ * DEPTH;
    const float* Kp = Kg + (size_t)bh * SEQ * DEPTH;
    const float* Vp = Vg + (size_t)bh * SEQ * DEPTH;
    float* Op = Og + (size_t)bh * SEQ * DEPTH;

    const int tid = threadIdx.x;
    const int warp = tid >> 5, lane = tid & 31;
    const int g = lane >> 2, t = lane & 3;
    const int wq0 = warp * 16;                 // warp's Q-row base in tile
    const unsigned FULL = 0xffffffffu;

    // ---- load Q tile into smem (one shot) ----
#pragma unroll
    for (int i = 0; i < 8; i++) {
        int id = tid + i * 256; int r = id >> 4, c = (id & 15) * 4;
        cp16(su(&Qs[r * QS_STRIDE + c]), Qp + (size_t)(m0 + r) * 64 + c);
    }
    cpcommit();

    // ---- prefetch KV tile 0 ----
#define KV_LOAD(buf, kv0)                                                         \
    do {                                                                          \
        _Pragma("unroll")                                                         \
        for (int i = 0; i < 8; i++) {                                             \
            int id = tid + i * 256; int r = id >> 4, c = (id & 15) * 4;           \
            cp16(su(&Ks[buf][r * KS_STRIDE + c]),                                 \
                 Kp + (size_t)((kv0) + r) * 64 + c);                              \
        }                                                                         \
        _Pragma("unroll")                                                         \
        for (int i = 0; i < 8; i++) {                                             \
            int id = tid + i * 256; int r = id >> 4, c = (id & 15) * 4;           \
            cp16(su(&Vs[buf][r * VS_STRIDE + c]),                                 \
                 Vp + (size_t)((kv0) + r) * 64 + c);                              \
        }                                                                         \
        cpcommit();                                                               \
    } while (0)

    KV_LOAD(0, 0);

    // Q commit was first group: wait for Q (and tile0 may still be in flight)
    cpwait1();
    __syncthreads();

    // ---- Q fragments in registers, pre-scaled by 1/sqrt(64)=0.125 (exact) ----
    unsigned aq[8][4];
#pragma unroll
    for (int kb = 0; kb < 8; kb++) {
        aq[kb][0] = __float_as_uint(0.125f * Qs[(wq0 + g) * QS_STRIDE + kb * 8 + t]);
        aq[kb][1] = __float_as_uint(0.125f * Qs[(wq0 + g + 8) * QS_STRIDE + kb * 8 + t]);
        aq[kb][2] = __float_as_uint(0.125f * Qs[(wq0 + g) * QS_STRIDE + kb * 8 + t + 4]);
        aq[kb][3] = __float_as_uint(0.125f * Qs[(wq0 + g + 8) * QS_STRIDE + kb * 8 + t + 4]);
    }

    // ---- softmax state + O accumulator ----
    float m0r = -1e30f, m1r = -1e30f, l0 = 0.f, l1 = 0.f;
    float o[8][4] = {};

    for (int j = 0; j < 16; j++) {
        if (j + 1 < 16) { KV_LOAD((j + 1) & 1, (j + 1) * 128); cpwait1(); }
        else cpwait0();
        __syncthreads();
        const float* ks = Ks[j & 1];
        const float* vs = Vs[j & 1];

        // ---- S = (Q/8) K^T : warp tile 16 x 128 ----
        float acc[16][4];
#pragma unroll
        for (int nb = 0; nb < 16; nb++)
#pragma unroll
            for (int i = 0; i < 4; i++) acc[nb][i] = 0.f;

#pragma unroll
        for (int kb = 0; kb < 8; kb++) {
#pragma unroll
            for (int nb = 0; nb < 16; nb++) {
                unsigned b[2];
                b[0] = __float_as_uint(ks[(nb * 8 + g) * KS_STRIDE + kb * 8 + t]);
                b[1] = __float_as_uint(ks[(nb * 8 + g) * KS_STRIDE + kb * 8 + t + 4]);
                mma8(acc[nb], aq[kb], b);
            }
        }

        // ---- online softmax (rows g and g+8) ----
        float mx0 = -1e30f, mx1 = -1e30f;
#pragma unroll
        for (int nb = 0; nb < 16; nb++) {
            mx0 = fmaxf(mx0, fmaxf(acc[nb][0], acc[nb][1]));
            mx1 = fmaxf(mx1, fmaxf(acc[nb][2], acc[nb][3]));
        }
        mx0 = fmaxf(mx0, __shfl_xor_sync(FULL, mx0, 1));
        mx0 = fmaxf(mx0, __shfl_xor_sync(FULL, mx0, 2));
        mx1 = fmaxf(mx1, __shfl_xor_sync(FULL, mx1, 1));
        mx1 = fmaxf(mx1, __shfl_xor_sync(FULL, mx1, 2));

        float mn0 = fmaxf(m0r, mx0), mn1 = fmaxf(m1r, mx1);
        float al0 = __expf(m0r - mn0), al1 = __expf(m1r - mn1);
        m0r = mn0; m1r = mn1;

        float s0 = 0.f, s1 = 0.f;
#pragma unroll
        for (int nb = 0; nb < 16; nb++) {
            float p0 = __expf(acc[nb][0] - mn0);
            float p1 = __expf(acc[nb][1] - mn0);
            float p2 = __expf(acc[nb][2] - mn1);
            float p3 = __expf(acc[nb][3] - mn1);
            s0 += p0 + p1; s1 += p2 + p3;
            acc[nb][0] = tf32r(p0); acc[nb][1] = tf32r(p1);
            acc[nb][2] = tf32r(p2); acc[nb][3] = tf32r(p3);
        }
        s0 += __shfl_xor_sync(FULL, s0, 1);
        s0 += __shfl_xor_sync(FULL, s0, 2);
        s1 += __shfl_xor_sync(FULL, s1, 1);
        s1 += __shfl_xor_sync(FULL, s1, 2);
        l0 = l0 * al0 + s0;
        l1 = l1 * al1 + s1;

        // rescale O
#pragma unroll
        for (int nb = 0; nb < 8; nb++) {
            o[nb][0] *= al0; o[nb][1] *= al0;
            o[nb][2] *= al1; o[nb][3] *= al1;
        }

        // ---- O += P @ V : convert C-frag P to A-frags via shuffles ----
        const int srcA = (lane & ~3) | (t >> 1);
        const int srcB = srcA + 2;
        const bool odd = (t & 1);
#pragma unroll
        for (int kb = 0; kb < 16; kb++) {
            float v0 = __shfl_sync(FULL, acc[kb][0], srcA);
            float v1 = __shfl_sync(FULL, acc[kb][1], srcA);
            float w0 = __shfl_sync(FULL, acc[kb][2], srcA);
            float w1 = __shfl_sync(FULL, acc[kb][3], srcA);
            float x0 = __shfl_sync(FULL, acc[kb][0], srcB);
            float x1 = __shfl_sync(FULL, acc[kb][1], srcB);
            float y0 = __shfl_sync(FULL, acc[kb][2], srcB);
            float y1 = __shfl_sync(FULL, acc[kb][3], srcB);
            unsigned ap[4];
            ap[0] = __float_as_uint(odd ? v1 : v0);
            ap[1] = __float_as_uint(odd ? w1 : w0);
            ap[2] = __float_as_uint(odd ? x1 : x0);
            ap[3] = __float_as_uint(odd ? y1 : y0);
#pragma unroll
            for (int nb = 0; nb < 8; nb++) {
                unsigned b[2];
                b[0] = __float_as_uint(vs[(kb * 8 + t) * VS_STRIDE + nb * 8 + g]);
                b[1] = __float_as_uint(vs[(kb * 8 + t + 4) * VS_STRIDE + nb * 8 + g]);
                mma8(o[nb], ap, b);
            }
        }
        __syncthreads();
    }

    // ---- epilogue: O /= l, round to tf32, store ----
    float inv0 = 1.f / l0, inv1 = 1.f / l1;
#pragma unroll
    for (int nb = 0; nb < 8; nb++) {
        int c0 = nb * 8 + t * 2;
        {
            int r = m0 + wq0 + g;
            float2 v;
            v.x = tf32r(o[nb][0] * inv0);
            v.y = tf32r(o[nb][1] * inv0);
            *(float2*)&Op[(size_t)r * 64 + c0] = v;
        }
        {
            int r = m0 + wq0 + g + 8;
            float2 v;
            v.x = tf32r(o[nb][2] * inv1);
            v.y = tf32r(o[nb][3] * inv1);
            *(float2*)&Op[(size_t)r * 64 + c0] = v;
        }
    }
}

// ============================================================
// Kernel 3: out = untranspose(Og) @ wo + bo, tf32 mma
// ============================================================
__global__ __launch_bounds__(256) void outproj_tc_kernel(
    const float* __restrict__ W, const float* __restrict__ bo,
    float* __restrict__ out)
{
    extern __shared__ float sm[];
    float* Asm[2] = { sm, sm + 4608 };
    float* Bsm[2] = { sm + 9216, sm + 9216 + 4352 };

    const int tid = threadIdx.x;
    const int m0 = blockIdx.y * 128, n0 = blockIdx.x * 128;
    const int warp = tid >> 5, lane = tid & 31;
    const int g = lane >> 2, t = lane & 3;
    const int wm = (warp & 3) * 32, wn = (warp >> 2) * 64;

    float acc[2][8][4] = {};

#define OP_LOAD(buf, k0)                                                          \
    do {                                                                          \
        _Pragma("unroll")                                                         \
        for (int i = 0; i < 4; i++) {                                             \
            int id = tid + i * 256; int r = id >> 3, cc = id & 7;                 \
            int m = m0 + r; int k = (k0) + cc * 4;                                \
            const float* src = Og + (((size_t)((m >> 11) * 16 + (k >> 6))) * 2048 \
                                     + (m & 2047)) * 64 + (k & 63);               \
            cp16(su(&Asm[buf][r * 36 + cc * 4]), src);                            \
        }                                                                         \
        _Pragma("unroll")                                                         \
        for (int i = 0; i < 4; i++) {                                             \
            int id = tid + i * 256; int r = id >> 5, cc = id & 31;                \
            cp16(su(&Bsm[buf][r * 136 + cc * 4]),                                 \
                 W + (size_t)((k0) + r) * 1024 + n0 + cc * 4);                    \
        }                                                                         \
        cpcommit();                                                               \
    } while (0)

    OP_LOAD(0, 0);
    for (int it = 0; it < 32; it++) {
        if (it + 1 < 32) { OP_LOAD((it + 1) & 1, (it + 1) * 32); cpwait1(); }
        else cpwait0();
        __syncthreads();
        const float* a_s = Asm[it & 1];
        const float* b_s = Bsm[it & 1];
#pragma unroll
        for (int ks = 0; ks < 32; ks += 8) {
            unsigned a[2][4], b[8][2];
#pragma unroll
            for (int ma = 0; ma < 2; ma++) {
                int rb = wm + ma * 16;
                a[ma][0] = __float_as_uint(a_s[(rb + g) * 36 + ks + t]);
                a[ma][1] = __float_as_uint(a_s[(rb + g + 8) * 36 + ks + t]);
                a[ma][2] = __float_as_uint(a_s[(rb + g) * 36 + ks + t + 4]);
                a[ma][3] = __float_as_uint(a_s[(rb + g + 8) * 36 + ks + t + 4]);
            }
#pragma unroll
            for (int nb = 0; nb < 8; nb++) {
                b[nb][0] = __float_as_uint(b_s[(ks + t) * 136 + wn + nb * 8 + g]);
                b[nb][1] = __float_as_uint(b_s[(ks + t + 4) * 136 + wn + nb * 8 + g]);
            }
#pragma unroll
            for (int nb = 0; nb < 8; nb++)
#pragma unroll
                for (int ma = 0; ma < 2; ma++)
                    mma8(acc[ma][nb], a[ma], b[nb]);
        }
        __syncthreads();
    }

#pragma unroll
    for (int ma = 0; ma < 2; ma++)
#pragma unroll
        for (int nb = 0; nb < 8; nb++) {
            int c0 = n0 + wn + nb * 8 + t * 2;
            float b0 = __ldg(&bo[c0]), b1 = __ldg(&bo[c0 + 1]);
#pragma unroll
            for (int rr = 0; rr < 2; rr++) {
                int r = m0 + wm + ma * 16 + g + rr * 8;
                float2 v;
                v.x = acc[ma][nb][rr * 2 + 0] + b0;
                v.y = acc[ma][nb][rr * 2 + 1] + b1;
                *(float2*)&out[(size_t)r * 1024 + c0] = v;
            }
        }
}

// ============================================================
extern "C" void kernel_launch(void* const* d_in, const int* in_sizes, int n_in,
                              void* d_out, int out_size)
{
    const float* x  = (const float*)d_in[0];
    const float* wq = (const float*)d_in[1];
    const float* bq = (const float*)d_in[2];
    const float* wk = (const float*)d_in[3];
    const float* bk = (const float*)d_in[4];
    const float* wv = (const float*)d_in[5];
    const float* bv = (const float*)d_in[6];
    const float* wo = (const float*)d_in[7];
    const float* bo = (const float*)d_in[8];
    float* out = (float*)d_out;

    cudaFuncSetAttribute(proj_tc_kernel,    cudaFuncAttributeMaxDynamicSharedMemorySize, 71680);
    cudaFuncSetAttribute(flash_attn_kernel, cudaFuncAttributeMaxDynamicSharedMemorySize, 178176);
    cudaFuncSetAttribute(outproj_tc_kernel, cudaFuncAttributeMaxDynamicSharedMemorySize, 71680);

    float* Xr_p; cudaGetSymbolAddress((void**)&Xr_p, Xr);
    float* Wr_p; cudaGetSymbolAddress((void**)&Wr_p, Wr);
    float* Qp;   cudaGetSymbolAddress((void**)&Qp, Qg);
    float* Kp;   cudaGetSymbolAddress((void**)&Kp, Kg);
    float* Vp;   cudaGetSymbolAddress((void**)&Vp, Vg);

    dim3 blk(256);
    const size_t WSZ = (size_t)D_MODEL * D_MODEL;

    // round inputs/weights to tf32 once
    {
        int n4 = (MROWS * D_MODEL) / 4;
        round_tf32_kernel<<<(n4 + 255) / 256, blk>>>(x, Xr_p, n4);
        int w4 = (int)(WSZ / 4);
        round_tf32_kernel<<<(w4 + 255) / 256, blk>>>(wq, Wr_p + 0 * WSZ, w4);
        round_tf32_kernel<<<(w4 + 255) / 256, blk>>>(wk, Wr_p + 1 * WSZ, w4);
        round_tf32_kernel<<<(w4 + 255) / 256, blk>>>(wv, Wr_p + 2 * WSZ, w4);
        round_tf32_kernel<<<(w4 + 255) / 256, blk>>>(wo, Wr_p + 3 * WSZ, w4);
    }

    dim3 gproj(D_MODEL / 128, MROWS / 128);  // (8, 64)
    proj_tc_kernel<<<gproj, blk, 71680>>>(Xr_p, Wr_p + 0 * WSZ, bq, Qp);
    proj_tc_kernel<<<gproj, blk, 71680>>>(Xr_p, Wr_p + 1 * WSZ, bk, Kp);
    proj_tc_kernel<<<gproj, blk, 71680>>>(Xr_p, Wr_p + 2 * WSZ, bv, Vp);

    flash_attn_kernel<<<dim3(SEQ / 128, BH), blk, 178176>>>();

    outproj_tc_kernel<<<gproj, blk, 71680>>>(Wr_p + 3 * WSZ, bo, out);
}